// round 10
// baseline (speedup 1.0000x reference)
#include <cuda_runtime.h>
#include <cuda_bf16.h>
#include <cstdint>
#include <cstddef>

#define HID   1024
#define NH    16
#define HD    64
#define BATCH 2
#define SEQ   2048
#define BH    (BATCH*NH)
#define MTOT  (BATCH*SEQ)

// packed split-bf16: low 16 bits = hi part, high 16 bits = lo part
__device__ __align__(16) uint32_t g_Xs[(size_t)MTOT * HID];
__device__ __align__(16) uint32_t g_Ws[3][(size_t)HID * HID];
__device__ __align__(16) uint32_t g_QKV[3][(size_t)BH * SEQ * HD];

__device__ __forceinline__ uint32_t packsplit(float x) {
    __nv_bfloat16 h = __float2bfloat16(x);
    __nv_bfloat16 l = __float2bfloat16(x - __bfloat162float(h));
    return (uint32_t)__bfloat16_as_ushort(h) | ((uint32_t)__bfloat16_as_ushort(l) << 16);
}
__device__ __forceinline__ void mma_bf16(float* d, const uint32_t* a, const uint32_t* b) {
    asm volatile("mma.sync.aligned.m16n8k16.row.col.f32.bf16.bf16.f32 "
        "{%0,%1,%2,%3}, {%4,%5,%6,%7}, {%8,%9}, {%0,%1,%2,%3};\n"
        : "+f"(d[0]), "+f"(d[1]), "+f"(d[2]), "+f"(d[3])
        : "r"(a[0]), "r"(a[1]), "r"(a[2]), "r"(a[3]), "r"(b[0]), "r"(b[1]));
}
__device__ __forceinline__ void ldsm_x4(uint32_t* r, uint32_t a) {
    asm volatile("ldmatrix.sync.aligned.m8n8.x4.shared.b16 {%0,%1,%2,%3}, [%4];\n"
                 : "=r"(r[0]), "=r"(r[1]), "=r"(r[2]), "=r"(r[3]) : "r"(a));
}
__device__ __forceinline__ void ldsm_x4_t(uint32_t* r, uint32_t a) {
    asm volatile("ldmatrix.sync.aligned.m8n8.x4.trans.shared.b16 {%0,%1,%2,%3}, [%4];\n"
                 : "=r"(r[0]), "=r"(r[1]), "=r"(r[2]), "=r"(r[3]) : "r"(a));
}
// store one staged uint4 of packed words as hi/lo halves (row stride 36 words)
__device__ __forceinline__ void stage_reg(uint32_t* sh, uint32_t* sl, int row, int q4, uint4 p) {
    uint2 hw = { __byte_perm(p.x, p.y, 0x5410), __byte_perm(p.z, p.w, 0x5410) };
    uint2 lw = { __byte_perm(p.x, p.y, 0x7632), __byte_perm(p.z, p.w, 0x7632) };
    *(uint2*)&sh[row*36 + q4*2] = hw;
    *(uint2*)&sl[row*36 + q4*2] = lw;
}

// ---------------- fp32 -> packed split-bf16 (X + 3 W in one launch) ---------
__global__ __launch_bounds__(256) void split_all_kernel(
    const float* __restrict__ X,  const float* __restrict__ Wq,
    const float* __restrict__ Wk, const float* __restrict__ Wv)
{
    const int nX4 = MTOT * HID / 4;       // 1048576
    const int nW4 = HID * HID / 4;        // 262144
    int i = blockIdx.x * 256 + threadIdx.x;
    const float* src; uint32_t* dst; int off;
    if (i < nX4) { src = X; dst = g_Xs; off = i; }
    else {
        int j = i - nX4;
        int w = j / nW4; off = j - w * nW4;
        src = (w == 0) ? Wq : (w == 1) ? Wk : Wv;
        dst = g_Ws[w];
    }
    float4 v = ((const float4*)src)[off];
    uint4 o = { packsplit(v.x), packsplit(v.y), packsplit(v.z), packsplit(v.w) };
    ((uint4*)dst)[off] = o;
}

// ---------------- QKV GEMM (tensor), Y = X W^T + b; Q scaled by 1/8 ---------
__global__ __launch_bounds__(256) void qkv_t_kernel(
    const float* __restrict__ bq, const float* __restrict__ bk, const float* __restrict__ bv)
{
    __shared__ __align__(16) uint32_t sXh[64*36], sXl[64*36], sWh[64*36], sWl[64*36];
    __shared__ float sBias[64];
    const int tid = threadIdx.x, lane = tid & 31, wid = tid >> 5;
    const int z = blockIdx.z, n0 = blockIdx.x * 64, m0 = blockIdx.y * 64;
    const int wm = wid & 3, wn = wid >> 2;
    const uint32_t* Wg = g_Ws[z];
    const float* bias = (z == 0) ? bq : (z == 1) ? bk : bv;
    uint32_t* outp = g_QKV[z];
    if (tid < 64) sBias[tid] = bias[n0 + tid];

    const uint32_t XhB = (uint32_t)__cvta_generic_to_shared(sXh);
    const uint32_t XlB = (uint32_t)__cvta_generic_to_shared(sXl);
    const uint32_t WhB = (uint32_t)__cvta_generic_to_shared(sWh);
    const uint32_t WlB = (uint32_t)__cvta_generic_to_shared(sWl);

    float acc[4][4];
    #pragma unroll
    for (int s = 0; s < 4; s++) { acc[s][0]=acc[s][1]=acc[s][2]=acc[s][3]=0.f; }

    const uint32_t a_byte = (uint32_t)(wm*16 + (lane & 7) + ((lane >> 3) & 1)*8)*144
                          + ((lane >> 4) & 1)*16;
    const uint32_t b_row  = (uint32_t)(wn*32 + ((lane >> 4) & 1)*8 + (lane & 7));
    const uint32_t b_kofs = ((lane >> 3) & 1)*16;

    const int srow = tid >> 4, sq4 = tid & 15;   // staging coords (4 rows apart per i)
    uint4 pX[4], pW[4];
    #pragma unroll
    for (int i = 0; i < 4; i++) {
        const int row = srow + i*16;
        pX[i] = *(const uint4*)(g_Xs + (size_t)(m0+row)*HID + sq4*4);
        pW[i] = *(const uint4*)(Wg   + (size_t)(n0+row)*HID + sq4*4);
    }

    for (int k0 = 0; k0 < HID; k0 += 64) {
        __syncthreads();
        #pragma unroll
        for (int i = 0; i < 4; i++) {
            stage_reg(sXh, sXl, srow + i*16, sq4, pX[i]);
            stage_reg(sWh, sWl, srow + i*16, sq4, pW[i]);
        }
        __syncthreads();
        if (k0 + 64 < HID) {
            #pragma unroll
            for (int i = 0; i < 4; i++) {
                const int row = srow + i*16;
                pX[i] = *(const uint4*)(g_Xs + (size_t)(m0+row)*HID + k0+64 + sq4*4);
                pW[i] = *(const uint4*)(Wg   + (size_t)(n0+row)*HID + k0+64 + sq4*4);
            }
        }
        #pragma unroll
        for (int kc = 0; kc < 4; kc++) {
            uint32_t Ah[4], Al[4];
            ldsm_x4(Ah, XhB + a_byte + kc*32);
            ldsm_x4(Al, XlB + a_byte + kc*32);
            #pragma unroll
            for (int sp = 0; sp < 2; sp++) {
                uint32_t Bh[4], Bl[4];
                uint32_t boff = (b_row + sp*16)*144 + b_kofs + kc*32;
                ldsm_x4(Bh, WhB + boff);
                ldsm_x4(Bl, WlB + boff);
                mma_bf16(acc[sp*2],   Ah, Bh);   mma_bf16(acc[sp*2],   Ah, Bl);
                mma_bf16(acc[sp*2],   Al, Bh);
                mma_bf16(acc[sp*2+1], Ah, Bh+2); mma_bf16(acc[sp*2+1], Ah, Bl+2);
                mma_bf16(acc[sp*2+1], Al, Bh+2);
            }
        }
    }
    const float qs = (z == 0) ? 0.125f : 1.0f;
    #pragma unroll
    for (int s = 0; s < 4; s++) {
        const int nl = wn*32 + s*8 + (lane & 3)*2, n = n0 + nl;
        const int h = n >> 6, d = n & 63;
        const float b0 = sBias[nl], b1 = sBias[nl+1];
        #pragma unroll
        for (int half = 0; half < 2; half++) {
            const int m = m0 + wm*16 + (lane >> 2) + half*8;
            const int bb = m >> 11, ss = m & (SEQ-1);
            uint2 w = { packsplit((acc[s][half*2]   + b0)*qs),
                        packsplit((acc[s][half*2+1] + b1)*qs) };
            *(uint2*)(outp + ((size_t)(bb*NH+h)*SEQ + ss)*HD + d) = w;
        }
    }
}

// -------- scores (tensor) + online stats + in-kernel normalization ----------
__global__ __launch_bounds__(256) void scores_t_kernel(float* __restrict__ Sbuf_all)
{
    __shared__ __align__(16) uint32_t sbuf[9216];
    __shared__ float2 sMS[64][2];
    __shared__ float2 sFin[64];
    const int tid = threadIdx.x, lane = tid & 31, wid = tid >> 5;
    const int bh = blockIdx.y, q0 = blockIdx.x * 64;
    const int wq = wid & 3, wk = wid >> 2;
    const uint32_t* Qg = g_QKV[0] + ((size_t)bh*SEQ + q0)*HD;
    const uint32_t* Kg = g_QKV[1] + (size_t)bh*SEQ*HD;
    float* Sbuf = Sbuf_all + ((size_t)bh*SEQ + q0)*SEQ;

    const uint32_t base = (uint32_t)__cvta_generic_to_shared(sbuf);
    uint32_t* sQh = sbuf; uint32_t* sQl = sbuf + 2304;
    uint32_t* sKh = sbuf; uint32_t* sKl = sbuf + 4608;
    const uint32_t QhB = base, QlB = base + 2304*4, KhB = base, KlB = base + 4608*4;

    #pragma unroll
    for (int i = 0; i < 4; i++) {
        int idx = tid + i*256, row = idx >> 4, q4 = idx & 15;
        stage_reg(sQh, sQl, row, q4, *(const uint4*)(Qg + (size_t)row*HD + q4*4));
    }
    __syncthreads();

    uint32_t Ah[4][4], Al[4][4];
    const uint32_t a_byte = (uint32_t)(wq*16 + (lane & 7) + ((lane >> 3) & 1)*8)*144
                          + ((lane >> 4) & 1)*16;
    #pragma unroll
    for (int kc = 0; kc < 4; kc++) { ldsm_x4(Ah[kc], QhB + a_byte + kc*32);
                                     ldsm_x4(Al[kc], QlB + a_byte + kc*32); }
    const uint32_t b_row  = (uint32_t)(((lane >> 4) & 1)*8 + (lane & 7));
    const uint32_t b_kofs = ((lane >> 3) & 1)*16;

    float m0r = -1e30f, s0r = 0.f, m1r = -1e30f, s1r = 0.f;

    for (int kt = 0; kt < 16; kt++) {
        __syncthreads();
        #pragma unroll
        for (int i = 0; i < 8; i++) {
            int idx = tid + i*256, row = idx >> 4, q4 = idx & 15;
            stage_reg(sKh, sKl, row, q4,
                      *(const uint4*)(Kg + (size_t)(kt*128 + row)*HD + q4*4));
        }
        __syncthreads();

        float acc[8][4];
        #pragma unroll
        for (int s = 0; s < 8; s++) { acc[s][0]=acc[s][1]=acc[s][2]=acc[s][3]=0.f; }
        #pragma unroll
        for (int kc = 0; kc < 4; kc++) {
            #pragma unroll
            for (int sp = 0; sp < 4; sp++) {
                uint32_t Bh[4], Bl[4];
                uint32_t boff = (uint32_t)(wk*64 + sp*16 + b_row)*144 + b_kofs + kc*32;
                ldsm_x4(Bh, KhB + boff);
                ldsm_x4(Bl, KlB + boff);
                mma_bf16(acc[sp*2],   Ah[kc], Bh);   mma_bf16(acc[sp*2],   Ah[kc], Bl);
                mma_bf16(acc[sp*2],   Al[kc], Bh);
                mma_bf16(acc[sp*2+1], Ah[kc], Bh+2); mma_bf16(acc[sp*2+1], Ah[kc], Bl+2);
                mma_bf16(acc[sp*2+1], Al[kc], Bh+2);
            }
        }
        const int r0 = wq*16 + (lane >> 2);
        #pragma unroll
        for (int s = 0; s < 8; s++) {
            const int col = kt*128 + wk*64 + s*8 + (lane & 3)*2;
            *(float2*)(Sbuf + (size_t)r0*SEQ + col)     = make_float2(acc[s][0], acc[s][1]);
            *(float2*)(Sbuf + (size_t)(r0+8)*SEQ + col) = make_float2(acc[s][2], acc[s][3]);
        }
        float t0 = -1e30f, t1 = -1e30f;
        #pragma unroll
        for (int s = 0; s < 8; s++) {
            t0 = fmaxf(t0, fmaxf(acc[s][0], acc[s][1]));
            t1 = fmaxf(t1, fmaxf(acc[s][2], acc[s][3]));
        }
        t0 = fmaxf(t0, __shfl_xor_sync(0xffffffffu, t0, 1));
        t0 = fmaxf(t0, __shfl_xor_sync(0xffffffffu, t0, 2));
        t1 = fmaxf(t1, __shfl_xor_sync(0xffffffffu, t1, 1));
        t1 = fmaxf(t1, __shfl_xor_sync(0xffffffffu, t1, 2));
        const float mn0 = fmaxf(m0r, t0), mn1 = fmaxf(m1r, t1);
        float e0 = 0.f, e1 = 0.f;
        #pragma unroll
        for (int s = 0; s < 8; s++) {
            e0 += __expf(acc[s][0]-mn0) + __expf(acc[s][1]-mn0);
            e1 += __expf(acc[s][2]-mn1) + __expf(acc[s][3]-mn1);
        }
        e0 += __shfl_xor_sync(0xffffffffu, e0, 1); e0 += __shfl_xor_sync(0xffffffffu, e0, 2);
        e1 += __shfl_xor_sync(0xffffffffu, e1, 1); e1 += __shfl_xor_sync(0xffffffffu, e1, 2);
        s0r = s0r * __expf(m0r - mn0) + e0; m0r = mn0;
        s1r = s1r * __expf(m1r - mn1) + e1; m1r = mn1;
    }
    __syncthreads();
    if ((lane & 3) == 0) {
        const int r0 = wq*16 + (lane >> 2);
        sMS[r0][wk]     = make_float2(m0r, s0r);
        sMS[r0 + 8][wk] = make_float2(m1r, s1r);
    }
    __syncthreads();
    if (tid < 64) {
        float2 a = sMS[tid][0], b = sMS[tid][1];
        float m = fmaxf(a.x, b.x);
        float s = a.y * __expf(a.x - m) + b.y * __expf(b.x - m);
        sFin[tid] = make_float2(m, 1.f / s);
    }
    __syncthreads();

    // phase 2: normalize this block's 64x2048 tile in place (L2-hot)
    #pragma unroll 4
    for (int i = 0; i < 128; i++) {
        const int idx = i*256 + tid;
        const int row = idx >> 9, c4 = idx & 511;
        const float2 st = sFin[row];
        float* gp = Sbuf + (size_t)row*SEQ + c4*4;
        float4 v = *(const float4*)gp;
        v.x = __expf(v.x - st.x) * st.y;
        v.y = __expf(v.y - st.x) * st.y;
        v.z = __expf(v.z - st.x) * st.y;
        v.w = __expf(v.w - st.x) * st.y;
        *(float4*)gp = v;
    }
}

// ---------------- P@V (tensor): read normalized probs, compute ctx ----------
__global__ __launch_bounds__(256) void pv_t_kernel(
    float* __restrict__ ctx_out, const float* __restrict__ Sbuf_all)
{
    __shared__ __align__(16) uint32_t sbuf[9216];
    const int tid = threadIdx.x, lane = tid & 31, wid = tid >> 5;
    const int bh = blockIdx.y, b = bh >> 4, h = bh & 15;
    const int q0 = blockIdx.x * 64;
    const int wq = wid & 3, wd = wid >> 2;
    const float* Sbuf = Sbuf_all + ((size_t)bh*SEQ + q0)*SEQ;
    const uint32_t* Vg = g_QKV[2] + (size_t)bh*SEQ*HD;

    const uint32_t base = (uint32_t)__cvta_generic_to_shared(sbuf);
    uint32_t* sPh = sbuf;        uint32_t* sPl = sbuf + 2304;
    uint32_t* sVh = sbuf + 4608; uint32_t* sVl = sbuf + 6912;
    const uint32_t PhB = base, PlB = base + 2304*4, VhB = base + 4608*4, VlB = base + 6912*4;

    float acc[4][4];
    #pragma unroll
    for (int s = 0; s < 4; s++) { acc[s][0]=acc[s][1]=acc[s][2]=acc[s][3]=0.f; }

    const uint32_t a_byte = (uint32_t)(wq*16 + (lane & 7) + ((lane >> 3) & 1)*8)*144
                          + ((lane >> 4) & 1)*16;
    const uint32_t bt_row = (uint32_t)((lane & 7) + ((lane >> 3) & 1)*8);
    const uint32_t bt_col = ((lane >> 4) & 1)*8;

    const int srow = tid >> 4, sq4 = tid & 15;
    float4 pP[4]; uint4 pV[4];
    #pragma unroll
    for (int i = 0; i < 4; i++) {
        const int row = srow + i*16;
        pP[i] = *(const float4*)(Sbuf + (size_t)row*SEQ + sq4*4);
        pV[i] = *(const uint4*)(Vg + (size_t)row*HD + sq4*4);
    }

    for (int kt = 0; kt < 32; kt++) {
        __syncthreads();
        #pragma unroll
        for (int i = 0; i < 4; i++) {
            const int row = srow + i*16;
            uint32_t s0 = packsplit(pP[i].x), s1 = packsplit(pP[i].y);
            uint32_t s2 = packsplit(pP[i].z), s3 = packsplit(pP[i].w);
            uint2 hw = { __byte_perm(s0, s1, 0x5410), __byte_perm(s2, s3, 0x5410) };
            uint2 lw = { __byte_perm(s0, s1, 0x7632), __byte_perm(s2, s3, 0x7632) };
            *(uint2*)&sPh[row*36 + sq4*2] = hw;
            *(uint2*)&sPl[row*36 + sq4*2] = lw;
            stage_reg(sVh, sVl, row, sq4, pV[i]);
        }
        __syncthreads();
        if (kt + 1 < 32) {
            #pragma unroll
            for (int i = 0; i < 4; i++) {
                const int row = srow + i*16;
                pP[i] = *(const float4*)(Sbuf + (size_t)row*SEQ + (kt+1)*64 + sq4*4);
                pV[i] = *(const uint4*)(Vg + (size_t)((kt+1)*64 + row)*HD + sq4*4);
            }
        }
        #pragma unroll
        for (int kc = 0; kc < 4; kc++) {
            uint32_t Ah[4], Al[4];
            ldsm_x4(Ah, PhB + a_byte + kc*32);
            ldsm_x4(Al, PlB + a_byte + kc*32);
            #pragma unroll
            for (int sp = 0; sp < 2; sp++) {
                uint32_t Bh[4], Bl[4];
                uint32_t boff = (uint32_t)(kc*16 + bt_row)*144
                              + (uint32_t)(wd*32 + sp*16 + bt_col)*2;
                ldsm_x4_t(Bh, VhB + boff);
                ldsm_x4_t(Bl, VlB + boff);
                mma_bf16(acc[sp*2],   Ah, Bh);   mma_bf16(acc[sp*2],   Ah, Bl);
                mma_bf16(acc[sp*2],   Al, Bh);
                mma_bf16(acc[sp*2+1], Ah, Bh+2); mma_bf16(acc[sp*2+1], Ah, Bl+2);
                mma_bf16(acc[sp*2+1], Al, Bh+2);
            }
        }
    }
    #pragma unroll
    for (int s = 0; s < 4; s++) {
        const int col = h*64 + wd*32 + s*8 + (lane & 3)*2;
        #pragma unroll
        for (int half = 0; half < 2; half++) {
            const int q = q0 + wq*16 + (lane >> 2) + half*8;
            *(float2*)(ctx_out + (size_t)(b*SEQ + q)*HID + col)
                = make_float2(acc[s][half*2], acc[s][half*2+1]);
        }
    }
}

// ---------------------------------------------------------------------------
extern "C" void kernel_launch(void* const* d_in, const int* in_sizes, int n_in,
                              void* d_out, int out_size)
{
    const float* X  = (const float*)d_in[0];
    const float* Wq = (const float*)d_in[1];
    const float* bq = (const float*)d_in[2];
    const float* Wk = (const float*)d_in[3];
    const float* bk = (const float*)d_in[4];
    const float* Wv = (const float*)d_in[5];
    const float* bv = (const float*)d_in[6];

    float* ctx   = (float*)d_out;
    float* probs = (float*)d_out + (size_t)BATCH * SEQ * HID;

    const int nTot4 = (MTOT * HID + 3 * HID * HID) / 4;   // 1835008
    split_all_kernel<<<nTot4 / 256, 256>>>(X, Wq, Wk, Wv);

    dim3 qkv_grid(HID/64, MTOT/64, 3);
    qkv_t_kernel<<<qkv_grid, 256>>>(bq, bk, bv);

    dim3 att_grid(SEQ/64, BH);
    scores_t_kernel<<<att_grid, 256>>>(probs);
    pv_t_kernel<<<att_grid, 256>>>(ctx, probs);
}

// round 11
// speedup vs baseline: 1.2742x; 1.2742x over previous
#include <cuda_runtime.h>
#include <cuda_bf16.h>
#include <cstdint>
#include <cstddef>

#define HID   1024
#define NH    16
#define HD    64
#define BATCH 2
#define SEQ   2048
#define BH    (BATCH*NH)
#define MTOT  (BATCH*SEQ)

// packed split-bf16: low 16 bits = hi part, high 16 bits = lo part
__device__ __align__(16) uint32_t g_Xs[(size_t)MTOT * HID];
__device__ __align__(16) uint32_t g_Ws[3][(size_t)HID * HID];
__device__ __align__(16) uint32_t g_QKV[3][(size_t)BH * SEQ * HD];

__device__ __forceinline__ uint32_t packsplit(float x) {
    __nv_bfloat16 h = __float2bfloat16(x);
    __nv_bfloat16 l = __float2bfloat16(x - __bfloat162float(h));
    return (uint32_t)__bfloat16_as_ushort(h) | ((uint32_t)__bfloat16_as_ushort(l) << 16);
}
__device__ __forceinline__ void mma_bf16(float* d, const uint32_t* a, const uint32_t* b) {
    asm volatile("mma.sync.aligned.m16n8k16.row.col.f32.bf16.bf16.f32 "
        "{%0,%1,%2,%3}, {%4,%5,%6,%7}, {%8,%9}, {%0,%1,%2,%3};\n"
        : "+f"(d[0]), "+f"(d[1]), "+f"(d[2]), "+f"(d[3])
        : "r"(a[0]), "r"(a[1]), "r"(a[2]), "r"(a[3]), "r"(b[0]), "r"(b[1]));
}
__device__ __forceinline__ void ldsm_x4(uint32_t* r, uint32_t a) {
    asm volatile("ldmatrix.sync.aligned.m8n8.x4.shared.b16 {%0,%1,%2,%3}, [%4];\n"
                 : "=r"(r[0]), "=r"(r[1]), "=r"(r[2]), "=r"(r[3]) : "r"(a));
}
__device__ __forceinline__ void ldsm_x4_t(uint32_t* r, uint32_t a) {
    asm volatile("ldmatrix.sync.aligned.m8n8.x4.trans.shared.b16 {%0,%1,%2,%3}, [%4];\n"
                 : "=r"(r[0]), "=r"(r[1]), "=r"(r[2]), "=r"(r[3]) : "r"(a));
}
// store one staged uint4 of packed words as hi/lo halves (row stride 36 words)
__device__ __forceinline__ void stage_reg(uint32_t* sh, uint32_t* sl, int row, int q4, uint4 p) {
    uint2 hw = { __byte_perm(p.x, p.y, 0x5410), __byte_perm(p.z, p.w, 0x5410) };
    uint2 lw = { __byte_perm(p.x, p.y, 0x7632), __byte_perm(p.z, p.w, 0x7632) };
    *(uint2*)&sh[row*36 + q4*2] = hw;
    *(uint2*)&sl[row*36 + q4*2] = lw;
}

// ---------------- fp32 -> packed split-bf16 (X + 3 W in one launch) ---------
__global__ __launch_bounds__(256) void split_all_kernel(
    const float* __restrict__ X,  const float* __restrict__ Wq,
    const float* __restrict__ Wk, const float* __restrict__ Wv)
{
    const int nX4 = MTOT * HID / 4;
    const int nW4 = HID * HID / 4;
    int i = blockIdx.x * 256 + threadIdx.x;
    const float* src; uint32_t* dst; int off;
    if (i < nX4) { src = X; dst = g_Xs; off = i; }
    else {
        int j = i - nX4;
        int w = j / nW4; off = j - w * nW4;
        src = (w == 0) ? Wq : (w == 1) ? Wk : Wv;
        dst = g_Ws[w];
    }
    float4 v = ((const float4*)src)[off];
    uint4 o = { packsplit(v.x), packsplit(v.y), packsplit(v.z), packsplit(v.w) };
    ((uint4*)dst)[off] = o;
}

// ---------------- QKV GEMM (tensor), Y = X W^T + b; Q scaled by 1/8 ---------
__global__ __launch_bounds__(256) void qkv_t_kernel(
    const float* __restrict__ bq, const float* __restrict__ bk, const float* __restrict__ bv)
{
    __shared__ __align__(16) uint32_t sXh[64*36], sXl[64*36], sWh[64*36], sWl[64*36];
    __shared__ float sBias[64];
    const int tid = threadIdx.x, lane = tid & 31, wid = tid >> 5;
    const int z = blockIdx.z, n0 = blockIdx.x * 64, m0 = blockIdx.y * 64;
    const int wm = wid & 3, wn = wid >> 2;
    const uint32_t* Wg = g_Ws[z];
    const float* bias = (z == 0) ? bq : (z == 1) ? bk : bv;
    uint32_t* outp = g_QKV[z];
    if (tid < 64) sBias[tid] = bias[n0 + tid];

    const uint32_t XhB = (uint32_t)__cvta_generic_to_shared(sXh);
    const uint32_t XlB = (uint32_t)__cvta_generic_to_shared(sXl);
    const uint32_t WhB = (uint32_t)__cvta_generic_to_shared(sWh);
    const uint32_t WlB = (uint32_t)__cvta_generic_to_shared(sWl);

    float acc[4][4];
    #pragma unroll
    for (int s = 0; s < 4; s++) { acc[s][0]=acc[s][1]=acc[s][2]=acc[s][3]=0.f; }

    const uint32_t a_byte = (uint32_t)(wm*16 + (lane & 7) + ((lane >> 3) & 1)*8)*144
                          + ((lane >> 4) & 1)*16;
    const uint32_t b_row  = (uint32_t)(wn*32 + ((lane >> 4) & 1)*8 + (lane & 7));
    const uint32_t b_kofs = ((lane >> 3) & 1)*16;

    const int srow = tid >> 4, sq4 = tid & 15;
    uint4 pX[4], pW[4];
    #pragma unroll
    for (int i = 0; i < 4; i++) {
        const int row = srow + i*16;
        pX[i] = *(const uint4*)(g_Xs + (size_t)(m0+row)*HID + sq4*4);
        pW[i] = *(const uint4*)(Wg   + (size_t)(n0+row)*HID + sq4*4);
    }

    for (int k0 = 0; k0 < HID; k0 += 64) {
        __syncthreads();
        #pragma unroll
        for (int i = 0; i < 4; i++) {
            stage_reg(sXh, sXl, srow + i*16, sq4, pX[i]);
            stage_reg(sWh, sWl, srow + i*16, sq4, pW[i]);
        }
        __syncthreads();
        if (k0 + 64 < HID) {
            #pragma unroll
            for (int i = 0; i < 4; i++) {
                const int row = srow + i*16;
                pX[i] = *(const uint4*)(g_Xs + (size_t)(m0+row)*HID + k0+64 + sq4*4);
                pW[i] = *(const uint4*)(Wg   + (size_t)(n0+row)*HID + k0+64 + sq4*4);
            }
        }
        #pragma unroll
        for (int kc = 0; kc < 4; kc++) {
            uint32_t Ah[4], Al[4];
            ldsm_x4(Ah, XhB + a_byte + kc*32);
            ldsm_x4(Al, XlB + a_byte + kc*32);
            #pragma unroll
            for (int sp = 0; sp < 2; sp++) {
                uint32_t Bh[4], Bl[4];
                uint32_t boff = (b_row + sp*16)*144 + b_kofs + kc*32;
                ldsm_x4(Bh, WhB + boff);
                ldsm_x4(Bl, WlB + boff);
                mma_bf16(acc[sp*2],   Ah, Bh);   mma_bf16(acc[sp*2],   Ah, Bl);
                mma_bf16(acc[sp*2],   Al, Bh);
                mma_bf16(acc[sp*2+1], Ah, Bh+2); mma_bf16(acc[sp*2+1], Ah, Bl+2);
                mma_bf16(acc[sp*2+1], Al, Bh+2);
            }
        }
    }
    const float qs = (z == 0) ? 0.125f : 1.0f;
    #pragma unroll
    for (int s = 0; s < 4; s++) {
        const int nl = wn*32 + s*8 + (lane & 3)*2, n = n0 + nl;
        const int h = n >> 6, d = n & 63;
        const float b0 = sBias[nl], b1 = sBias[nl+1];
        #pragma unroll
        for (int half = 0; half < 2; half++) {
            const int m = m0 + wm*16 + (lane >> 2) + half*8;
            const int bb = m >> 11, ss = m & (SEQ-1);
            uint2 w = { packsplit((acc[s][half*2]   + b0)*qs),
                        packsplit((acc[s][half*2+1] + b1)*qs) };
            *(uint2*)(outp + ((size_t)(bb*NH+h)*SEQ + ss)*HD + d) = w;
        }
    }
}

// ---- fused attention: phase1 scores+stats, phase2 normalize+probs+P@V ------
__global__ __launch_bounds__(256) void attn_fused_kernel(
    float* __restrict__ ctx_out, float* __restrict__ Sbuf_all)
{
    __shared__ __align__(16) uint32_t sbuf[9216];
    __shared__ float2 sMS[64][2];
    __shared__ float2 sFin[64];
    const int tid = threadIdx.x, lane = tid & 31, wid = tid >> 5;
    const int bh = blockIdx.y, q0 = blockIdx.x * 64;
    const int b = bh >> 4, h = bh & 15;
    const int wq = wid & 3, wk = wid >> 2;
    const uint32_t* Qg = g_QKV[0] + ((size_t)bh*SEQ + q0)*HD;
    const uint32_t* Kg = g_QKV[1] + (size_t)bh*SEQ*HD;
    const uint32_t* Vg = g_QKV[2] + (size_t)bh*SEQ*HD;
    float* Sbuf = Sbuf_all + ((size_t)bh*SEQ + q0)*SEQ;

    const uint32_t base = (uint32_t)__cvta_generic_to_shared(sbuf);
    uint32_t* sQh = sbuf; uint32_t* sQl = sbuf + 2304;
    uint32_t* sKh = sbuf; uint32_t* sKl = sbuf + 4608;
    const uint32_t QhB = base, QlB = base + 2304*4, KhB = base, KlB = base + 4608*4;

    // ======================= Phase 1: scores + stats =======================
    #pragma unroll
    for (int i = 0; i < 4; i++) {
        int idx = tid + i*256, row = idx >> 4, q4 = idx & 15;
        stage_reg(sQh, sQl, row, q4, *(const uint4*)(Qg + (size_t)row*HD + q4*4));
    }
    __syncthreads();

    uint32_t Ah[4][4], Al[4][4];
    const uint32_t a_byte = (uint32_t)(wq*16 + (lane & 7) + ((lane >> 3) & 1)*8)*144
                          + ((lane >> 4) & 1)*16;
    #pragma unroll
    for (int kc = 0; kc < 4; kc++) { ldsm_x4(Ah[kc], QhB + a_byte + kc*32);
                                     ldsm_x4(Al[kc], QlB + a_byte + kc*32); }
    const uint32_t b_row  = (uint32_t)(((lane >> 4) & 1)*8 + (lane & 7));
    const uint32_t b_kofs = ((lane >> 3) & 1)*16;

    float m0r = -1e30f, s0r = 0.f, m1r = -1e30f, s1r = 0.f;

    for (int kt = 0; kt < 16; kt++) {
        __syncthreads();
        #pragma unroll
        for (int i = 0; i < 8; i++) {
            int idx = tid + i*256, row = idx >> 4, q4 = idx & 15;
            stage_reg(sKh, sKl, row, q4,
                      *(const uint4*)(Kg + (size_t)(kt*128 + row)*HD + q4*4));
        }
        __syncthreads();

        float acc[8][4];
        #pragma unroll
        for (int s = 0; s < 8; s++) { acc[s][0]=acc[s][1]=acc[s][2]=acc[s][3]=0.f; }
        #pragma unroll
        for (int kc = 0; kc < 4; kc++) {
            #pragma unroll
            for (int sp = 0; sp < 4; sp++) {
                uint32_t Bh[4], Bl[4];
                uint32_t boff = (uint32_t)(wk*64 + sp*16 + b_row)*144 + b_kofs + kc*32;
                ldsm_x4(Bh, KhB + boff);
                ldsm_x4(Bl, KlB + boff);
                mma_bf16(acc[sp*2],   Ah[kc], Bh);   mma_bf16(acc[sp*2],   Ah[kc], Bl);
                mma_bf16(acc[sp*2],   Al[kc], Bh);
                mma_bf16(acc[sp*2+1], Ah[kc], Bh+2); mma_bf16(acc[sp*2+1], Ah[kc], Bl+2);
                mma_bf16(acc[sp*2+1], Al[kc], Bh+2);
            }
        }
        const int r0 = wq*16 + (lane >> 2);
        #pragma unroll
        for (int s = 0; s < 8; s++) {
            const int col = kt*128 + wk*64 + s*8 + (lane & 3)*2;
            *(float2*)(Sbuf + (size_t)r0*SEQ + col)     = make_float2(acc[s][0], acc[s][1]);
            *(float2*)(Sbuf + (size_t)(r0+8)*SEQ + col) = make_float2(acc[s][2], acc[s][3]);
        }
        float t0 = -1e30f, t1 = -1e30f;
        #pragma unroll
        for (int s = 0; s < 8; s++) {
            t0 = fmaxf(t0, fmaxf(acc[s][0], acc[s][1]));
            t1 = fmaxf(t1, fmaxf(acc[s][2], acc[s][3]));
        }
        t0 = fmaxf(t0, __shfl_xor_sync(0xffffffffu, t0, 1));
        t0 = fmaxf(t0, __shfl_xor_sync(0xffffffffu, t0, 2));
        t1 = fmaxf(t1, __shfl_xor_sync(0xffffffffu, t1, 1));
        t1 = fmaxf(t1, __shfl_xor_sync(0xffffffffu, t1, 2));
        const float mn0 = fmaxf(m0r, t0), mn1 = fmaxf(m1r, t1);
        float e0 = 0.f, e1 = 0.f;
        #pragma unroll
        for (int s = 0; s < 8; s++) {
            e0 += __expf(acc[s][0]-mn0) + __expf(acc[s][1]-mn0);
            e1 += __expf(acc[s][2]-mn1) + __expf(acc[s][3]-mn1);
        }
        e0 += __shfl_xor_sync(0xffffffffu, e0, 1); e0 += __shfl_xor_sync(0xffffffffu, e0, 2);
        e1 += __shfl_xor_sync(0xffffffffu, e1, 1); e1 += __shfl_xor_sync(0xffffffffu, e1, 2);
        s0r = s0r * __expf(m0r - mn0) + e0; m0r = mn0;
        s1r = s1r * __expf(m1r - mn1) + e1; m1r = mn1;
    }
    __syncthreads();
    if ((lane & 3) == 0) {
        const int r0 = wq*16 + (lane >> 2);
        sMS[r0][wk]     = make_float2(m0r, s0r);
        sMS[r0 + 8][wk] = make_float2(m1r, s1r);
    }
    __syncthreads();
    if (tid < 64) {
        float2 a = sMS[tid][0], bb2 = sMS[tid][1];
        float m = fmaxf(a.x, bb2.x);
        float s = a.y * __expf(a.x - m) + bb2.y * __expf(bb2.x - m);
        sFin[tid] = make_float2(m, 1.f / s);
    }
    __syncthreads();

    // ============ Phase 2: normalize + write probs + P@V (kt reversed) =====
    uint32_t* sPh = sbuf;        uint32_t* sPl = sbuf + 2304;
    uint32_t* sVh = sbuf + 4608; uint32_t* sVl = sbuf + 6912;
    const uint32_t PhB = base, PlB = base + 2304*4, VhB = base + 4608*4, VlB = base + 6912*4;
    const int wd = wk;

    float acc2[4][4];
    #pragma unroll
    for (int s = 0; s < 4; s++) { acc2[s][0]=acc2[s][1]=acc2[s][2]=acc2[s][3]=0.f; }

    const uint32_t bt_row = (uint32_t)((lane & 7) + ((lane >> 3) & 1)*8);
    const uint32_t bt_col = ((lane >> 4) & 1)*8;
    const int srow = tid >> 4, sq4 = tid & 15;

    float4 pP[4]; uint4 pV[4];
    #pragma unroll
    for (int i = 0; i < 4; i++) {
        const int row = srow + i*16;
        pP[i] = *(const float4*)(Sbuf + (size_t)row*SEQ + 31*64 + sq4*4);
        pV[i] = *(const uint4*)(Vg + (size_t)(31*64 + row)*HD + sq4*4);
    }

    for (int t = 0; t < 32; t++) {
        const int kt = 31 - t;
        __syncthreads();
        #pragma unroll
        for (int i = 0; i < 4; i++) {
            const int row = srow + i*16;
            const float2 st = sFin[row];
            float p0 = __expf(pP[i].x - st.x) * st.y;
            float p1 = __expf(pP[i].y - st.x) * st.y;
            float p2 = __expf(pP[i].z - st.x) * st.y;
            float p3 = __expf(pP[i].w - st.x) * st.y;
            __stcs((float4*)(Sbuf + (size_t)row*SEQ + kt*64 + sq4*4),
                   make_float4(p0, p1, p2, p3));
            uint32_t s0 = packsplit(p0), s1 = packsplit(p1);
            uint32_t s2 = packsplit(p2), s3 = packsplit(p3);
            uint2 hw = { __byte_perm(s0, s1, 0x5410), __byte_perm(s2, s3, 0x5410) };
            uint2 lw = { __byte_perm(s0, s1, 0x7632), __byte_perm(s2, s3, 0x7632) };
            *(uint2*)&sPh[row*36 + sq4*2] = hw;
            *(uint2*)&sPl[row*36 + sq4*2] = lw;
            stage_reg(sVh, sVl, row, sq4, pV[i]);
        }
        __syncthreads();
        if (t + 1 < 32) {
            const int ktn = kt - 1;
            #pragma unroll
            for (int i = 0; i < 4; i++) {
                const int row = srow + i*16;
                pP[i] = *(const float4*)(Sbuf + (size_t)row*SEQ + ktn*64 + sq4*4);
                pV[i] = *(const uint4*)(Vg + (size_t)(ktn*64 + row)*HD + sq4*4);
            }
        }
        #pragma unroll
        for (int kc = 0; kc < 4; kc++) {
            uint32_t Ph[4], Pl[4];
            ldsm_x4(Ph, PhB + a_byte + kc*32);
            ldsm_x4(Pl, PlB + a_byte + kc*32);
            #pragma unroll
            for (int sp = 0; sp < 2; sp++) {
                uint32_t Bh[4], Bl[4];
                uint32_t boff = (uint32_t)(kc*16 + bt_row)*144
                              + (uint32_t)(wd*32 + sp*16 + bt_col)*2;
                ldsm_x4_t(Bh, VhB + boff);
                ldsm_x4_t(Bl, VlB + boff);
                mma_bf16(acc2[sp*2],   Ph, Bh);   mma_bf16(acc2[sp*2],   Ph, Bl);
                mma_bf16(acc2[sp*2],   Pl, Bh);
                mma_bf16(acc2[sp*2+1], Ph, Bh+2); mma_bf16(acc2[sp*2+1], Ph, Bl+2);
                mma_bf16(acc2[sp*2+1], Pl, Bh+2);
            }
        }
    }
    #pragma unroll
    for (int s = 0; s < 4; s++) {
        const int col = h*64 + wd*32 + s*8 + (lane & 3)*2;
        #pragma unroll
        for (int half = 0; half < 2; half++) {
            const int q = q0 + wq*16 + (lane >> 2) + half*8;
            __stcs((float2*)(ctx_out + (size_t)(b*SEQ + q)*HID + col),
                   make_float2(acc2[s][half*2], acc2[s][half*2+1]));
        }
    }
}

// ---------------------------------------------------------------------------
extern "C" void kernel_launch(void* const* d_in, const int* in_sizes, int n_in,
                              void* d_out, int out_size)
{
    const float* X  = (const float*)d_in[0];
    const float* Wq = (const float*)d_in[1];
    const float* bq = (const float*)d_in[2];
    const float* Wk = (const float*)d_in[3];
    const float* bk = (const float*)d_in[4];
    const float* Wv = (const float*)d_in[5];
    const float* bv = (const float*)d_in[6];

    float* ctx   = (float*)d_out;
    float* probs = (float*)d_out + (size_t)BATCH * SEQ * HID;

    const int nTot4 = (MTOT * HID + 3 * HID * HID) / 4;
    split_all_kernel<<<nTot4 / 256, 256>>>(X, Wq, Wk, Wv);

    dim3 qkv_grid(HID/64, MTOT/64, 3);
    qkv_t_kernel<<<qkv_grid, 256>>>(bq, bk, bv);

    dim3 att_grid(SEQ/64, BH);
    attn_fused_kernel<<<att_grid, 256>>>(ctx, probs);
}

// round 12
// speedup vs baseline: 1.3127x; 1.0302x over previous
#include <cuda_runtime.h>
#include <cuda_bf16.h>
#include <cstdint>
#include <cstddef>

#define HID   1024
#define NH    16
#define HD    64
#define BATCH 2
#define SEQ   2048
#define BH    (BATCH*NH)
#define MTOT  (BATCH*SEQ)

#define STAGE_W 9216u     /* words per pipeline stage  */
#define STAGE_B 36864u    /* bytes per pipeline stage  */
#define DSMEM_B (3*STAGE_B)

// hi/lo split-bf16 stored as separate arrays (pure-copy staging)
__device__ __align__(16) __nv_bfloat16 g_Xh[(size_t)MTOT * HID];
__device__ __align__(16) __nv_bfloat16 g_Xl[(size_t)MTOT * HID];
__device__ __align__(16) __nv_bfloat16 g_Wh[3][(size_t)HID * HID];
__device__ __align__(16) __nv_bfloat16 g_Wl[3][(size_t)HID * HID];
__device__ __align__(16) __nv_bfloat16 g_QKVh[3][(size_t)BH * SEQ * HD];
__device__ __align__(16) __nv_bfloat16 g_QKVl[3][(size_t)BH * SEQ * HD];

__device__ __forceinline__ void split2(float a, float b, uint32_t& hw, uint32_t& lw) {
    __nv_bfloat16 ha = __float2bfloat16(a), hb = __float2bfloat16(b);
    hw = (uint32_t)__bfloat16_as_ushort(ha) | ((uint32_t)__bfloat16_as_ushort(hb) << 16);
    __nv_bfloat16 la = __float2bfloat16(a - __bfloat162float(ha));
    __nv_bfloat16 lb = __float2bfloat16(b - __bfloat162float(hb));
    lw = (uint32_t)__bfloat16_as_ushort(la) | ((uint32_t)__bfloat16_as_ushort(lb) << 16);
}
__device__ __forceinline__ void mma_bf16(float* d, const uint32_t* a, const uint32_t* b) {
    asm volatile("mma.sync.aligned.m16n8k16.row.col.f32.bf16.bf16.f32 "
        "{%0,%1,%2,%3}, {%4,%5,%6,%7}, {%8,%9}, {%0,%1,%2,%3};\n"
        : "+f"(d[0]), "+f"(d[1]), "+f"(d[2]), "+f"(d[3])
        : "r"(a[0]), "r"(a[1]), "r"(a[2]), "r"(a[3]), "r"(b[0]), "r"(b[1]));
}
__device__ __forceinline__ void ldsm_x4(uint32_t* r, uint32_t a) {
    asm volatile("ldmatrix.sync.aligned.m8n8.x4.shared.b16 {%0,%1,%2,%3}, [%4];\n"
                 : "=r"(r[0]), "=r"(r[1]), "=r"(r[2]), "=r"(r[3]) : "r"(a));
}
__device__ __forceinline__ void ldsm_x4_t(uint32_t* r, uint32_t a) {
    asm volatile("ldmatrix.sync.aligned.m8n8.x4.trans.shared.b16 {%0,%1,%2,%3}, [%4];\n"
                 : "=r"(r[0]), "=r"(r[1]), "=r"(r[2]), "=r"(r[3]) : "r"(a));
}
__device__ __forceinline__ void cp16(uint32_t dst, const void* src) {
    asm volatile("cp.async.cg.shared.global [%0], [%1], 16;\n" :: "r"(dst), "l"(src));
}
#define CP_COMMIT() asm volatile("cp.async.commit_group;\n")
#define CP_WAIT1()  asm volatile("cp.async.wait_group 1;\n")
#define CP_WAIT0()  asm volatile("cp.async.wait_all;\n")

// ---------------- fp32 -> hi/lo bf16 (X + 3 W in one launch) ----------------
__global__ __launch_bounds__(256) void split_all_kernel(
    const float* __restrict__ X,  const float* __restrict__ Wq,
    const float* __restrict__ Wk, const float* __restrict__ Wv)
{
    const int nX4 = MTOT * HID / 4;
    const int nW4 = HID * HID / 4;
    int i = blockIdx.x * 256 + threadIdx.x;
    const float* src; __nv_bfloat16 *dh, *dl; int off;
    if (i < nX4) { src = X; dh = g_Xh; dl = g_Xl; off = i; }
    else {
        int j = i - nX4;
        int w = j / nW4; off = j - w * nW4;
        src = (w == 0) ? Wq : (w == 1) ? Wk : Wv;
        dh = g_Wh[w]; dl = g_Wl[w];
    }
    float4 v = ((const float4*)src)[off];
    uint32_t h0, l0, h1, l1;
    split2(v.x, v.y, h0, l0);
    split2(v.z, v.w, h1, l1);
    *(uint2*)(dh + (size_t)off*4) = make_uint2(h0, h1);
    *(uint2*)(dl + (size_t)off*4) = make_uint2(l0, l1);
}

// ---------------- QKV GEMM (tensor, cp.async 3-stage) -----------------------
__global__ __launch_bounds__(256) void qkv_t_kernel(
    const float* __restrict__ bq, const float* __restrict__ bk, const float* __restrict__ bv)
{
    extern __shared__ __align__(16) uint32_t dsm[];
    __shared__ float sBias[64];
    const int tid = threadIdx.x, lane = tid & 31, wid = tid >> 5;
    const int z = blockIdx.z, n0 = blockIdx.x * 64, m0 = blockIdx.y * 64;
    const int wm = wid & 3, wn = wid >> 2;
    const float* bias = (z == 0) ? bq : (z == 1) ? bk : bv;
    if (tid < 64) sBias[tid] = bias[n0 + tid];

    const char* XhG = (const char*)g_Xh;
    const char* XlG = (const char*)g_Xl;
    const char* WhG = (const char*)g_Wh[z];
    const char* WlG = (const char*)g_Wl[z];
    const uint32_t dbase = (uint32_t)__cvta_generic_to_shared(dsm);

    const int srow = tid >> 3, sc16 = tid & 7;
    // issue one 64x64 X+W tile (hi+lo) into stage s
    auto issueXW = [&](int k, int s) {
        #pragma unroll
        for (int p = 0; p < 2; p++) {
            const int row = srow + p*32, c16 = sc16;
            const uint32_t d = dbase + (uint32_t)s*STAGE_B + row*144 + c16*16;
            const size_t xo = (size_t)(m0+row)*2048 + k*128 + c16*16;
            const size_t wo = (size_t)(n0+row)*2048 + k*128 + c16*16;
            cp16(d,         XhG + xo);
            cp16(d +  9216, XlG + xo);
            cp16(d + 18432, WhG + wo);
            cp16(d + 27648, WlG + wo);
        }
    };

    float acc[4][4];
    #pragma unroll
    for (int s = 0; s < 4; s++) { acc[s][0]=acc[s][1]=acc[s][2]=acc[s][3]=0.f; }

    const uint32_t a_byte = (uint32_t)(wm*16 + (lane & 7) + ((lane >> 3) & 1)*8)*144
                          + ((lane >> 4) & 1)*16;
    const uint32_t b_row  = (uint32_t)(wn*32 + ((lane >> 4) & 1)*8 + (lane & 7));
    const uint32_t b_kofs = ((lane >> 3) & 1)*16;

    issueXW(0, 0); CP_COMMIT();
    issueXW(1, 1); CP_COMMIT();

    for (int k = 0; k < 16; k++) {
        CP_WAIT1();
        __syncthreads();
        if (k + 2 < 16) issueXW(k + 2, (k + 2) % 3);
        CP_COMMIT();
        const uint32_t XhB = dbase + (uint32_t)(k % 3)*STAGE_B;
        const uint32_t XlB = XhB + 9216, WhB = XhB + 18432, WlB = XhB + 27648;
        #pragma unroll
        for (int kc = 0; kc < 4; kc++) {
            uint32_t Ah[4], Al[4];
            ldsm_x4(Ah, XhB + a_byte + kc*32);
            ldsm_x4(Al, XlB + a_byte + kc*32);
            #pragma unroll
            for (int sp = 0; sp < 2; sp++) {
                uint32_t Bh[4], Bl[4];
                uint32_t boff = (b_row + sp*16)*144 + b_kofs + kc*32;
                ldsm_x4(Bh, WhB + boff);
                ldsm_x4(Bl, WlB + boff);
                mma_bf16(acc[sp*2],   Ah, Bh);   mma_bf16(acc[sp*2],   Ah, Bl);
                mma_bf16(acc[sp*2],   Al, Bh);
                mma_bf16(acc[sp*2+1], Ah, Bh+2); mma_bf16(acc[sp*2+1], Ah, Bl+2);
                mma_bf16(acc[sp*2+1], Al, Bh+2);
            }
        }
    }
    const float qs = (z == 0) ? 0.125f : 1.0f;
    #pragma unroll
    for (int s = 0; s < 4; s++) {
        const int nl = wn*32 + s*8 + (lane & 3)*2, n = n0 + nl;
        const int h = n >> 6, d = n & 63;
        const float b0 = sBias[nl], b1 = sBias[nl+1];
        #pragma unroll
        for (int half = 0; half < 2; half++) {
            const int m = m0 + wm*16 + (lane >> 2) + half*8;
            const int bb = m >> 11, ss = m & (SEQ-1);
            const size_t ofs = ((size_t)(bb*NH+h)*SEQ + ss)*HD + d;
            uint32_t hw, lw;
            split2((acc[s][half*2] + b0)*qs, (acc[s][half*2+1] + b1)*qs, hw, lw);
            *(uint32_t*)(g_QKVh[z] + ofs) = hw;
            *(uint32_t*)(g_QKVl[z] + ofs) = lw;
        }
    }
}

// ---- fused attention: phase1 scores+stats, phase2 normalize+probs+P@V ------
__global__ __launch_bounds__(256) void attn_fused_kernel(
    float* __restrict__ ctx_out, float* __restrict__ Sbuf_all)
{
    extern __shared__ __align__(16) uint32_t dsm[];
    __shared__ float2 sMS[64][2];
    __shared__ float2 sFin[64];
    const int tid = threadIdx.x, lane = tid & 31, wid = tid >> 5;
    const int bh = blockIdx.y, q0 = blockIdx.x * 64;
    const int b = bh >> 4, h = bh & 15;
    const int wq = wid & 3, wk = wid >> 2;
    const char* QhG = (const char*)g_QKVh[0] + ((size_t)bh*SEQ + q0)*HD*2;
    const char* QlG = (const char*)g_QKVl[0] + ((size_t)bh*SEQ + q0)*HD*2;
    const char* KhG = (const char*)g_QKVh[1] + (size_t)bh*SEQ*HD*2;
    const char* KlG = (const char*)g_QKVl[1] + (size_t)bh*SEQ*HD*2;
    const char* VhG = (const char*)g_QKVh[2] + (size_t)bh*SEQ*HD*2;
    const char* VlG = (const char*)g_QKVl[2] + (size_t)bh*SEQ*HD*2;
    float* Sbuf = Sbuf_all + ((size_t)bh*SEQ + q0)*SEQ;

    const uint32_t dbase = (uint32_t)__cvta_generic_to_shared(dsm);
    const int srow8 = tid >> 3, sc16 = tid & 7;   // copy coords (8x16B rows)
    const int srow  = tid >> 4, sq4  = tid & 15;  // P-staging coords

    // ---------------- stage Q (blocking, one time) ----------------
    #pragma unroll
    for (int p = 0; p < 2; p++) {
        const int row = srow8 + p*32;
        const uint32_t d = dbase + row*144 + sc16*16;
        cp16(d,        QhG + (size_t)row*128 + sc16*16);
        cp16(d + 9216, QlG + (size_t)row*128 + sc16*16);
    }
    CP_COMMIT(); CP_WAIT0();
    __syncthreads();

    uint32_t Ah[4][4], Al[4][4];
    const uint32_t a_byte = (uint32_t)(wq*16 + (lane & 7) + ((lane >> 3) & 1)*8)*144
                          + ((lane >> 4) & 1)*16;
    #pragma unroll
    for (int kc = 0; kc < 4; kc++) {
        ldsm_x4(Ah[kc], dbase + a_byte + kc*32);
        ldsm_x4(Al[kc], dbase + 9216 + a_byte + kc*32);
    }
    __syncthreads();

    // ---------------- phase 1: K pipeline ----------------
    auto issueK = [&](int kt, int s) {
        #pragma unroll
        for (int p = 0; p < 4; p++) {
            const int row = srow8 + p*32;
            const uint32_t d = dbase + (uint32_t)s*STAGE_B + row*144 + sc16*16;
            const size_t ko = (size_t)(kt*128 + row)*128 + sc16*16;
            cp16(d,         KhG + ko);
            cp16(d + 18432, KlG + ko);
        }
    };
    const uint32_t b_row  = (uint32_t)(((lane >> 4) & 1)*8 + (lane & 7));
    const uint32_t b_kofs = ((lane >> 3) & 1)*16;

    issueK(0, 0); CP_COMMIT();
    issueK(1, 1); CP_COMMIT();

    float m0r = -1e30f, s0r = 0.f, m1r = -1e30f, s1r = 0.f;

    for (int kt = 0; kt < 16; kt++) {
        CP_WAIT1();
        __syncthreads();
        if (kt + 2 < 16) issueK(kt + 2, (kt + 2) % 3);
        CP_COMMIT();
        const uint32_t KhB = dbase + (uint32_t)(kt % 3)*STAGE_B;
        const uint32_t KlB = KhB + 18432;

        float acc[8][4];
        #pragma unroll
        for (int s = 0; s < 8; s++) { acc[s][0]=acc[s][1]=acc[s][2]=acc[s][3]=0.f; }
        #pragma unroll
        for (int kc = 0; kc < 4; kc++) {
            #pragma unroll
            for (int sp = 0; sp < 4; sp++) {
                uint32_t Bh[4], Bl[4];
                uint32_t boff = (uint32_t)(wk*64 + sp*16 + b_row)*144 + b_kofs + kc*32;
                ldsm_x4(Bh, KhB + boff);
                ldsm_x4(Bl, KlB + boff);
                mma_bf16(acc[sp*2],   Ah[kc], Bh);   mma_bf16(acc[sp*2],   Ah[kc], Bl);
                mma_bf16(acc[sp*2],   Al[kc], Bh);
                mma_bf16(acc[sp*2+1], Ah[kc], Bh+2); mma_bf16(acc[sp*2+1], Ah[kc], Bl+2);
                mma_bf16(acc[sp*2+1], Al[kc], Bh+2);
            }
        }
        const int r0 = wq*16 + (lane >> 2);
        #pragma unroll
        for (int s = 0; s < 8; s++) {
            const int col = kt*128 + wk*64 + s*8 + (lane & 3)*2;
            *(float2*)(Sbuf + (size_t)r0*SEQ + col)     = make_float2(acc[s][0], acc[s][1]);
            *(float2*)(Sbuf + (size_t)(r0+8)*SEQ + col) = make_float2(acc[s][2], acc[s][3]);
        }
        float t0 = -1e30f, t1 = -1e30f;
        #pragma unroll
        for (int s = 0; s < 8; s++) {
            t0 = fmaxf(t0, fmaxf(acc[s][0], acc[s][1]));
            t1 = fmaxf(t1, fmaxf(acc[s][2], acc[s][3]));
        }
        t0 = fmaxf(t0, __shfl_xor_sync(0xffffffffu, t0, 1));
        t0 = fmaxf(t0, __shfl_xor_sync(0xffffffffu, t0, 2));
        t1 = fmaxf(t1, __shfl_xor_sync(0xffffffffu, t1, 1));
        t1 = fmaxf(t1, __shfl_xor_sync(0xffffffffu, t1, 2));
        const float mn0 = fmaxf(m0r, t0), mn1 = fmaxf(m1r, t1);
        float e0 = 0.f, e1 = 0.f;
        #pragma unroll
        for (int s = 0; s < 8; s++) {
            e0 += __expf(acc[s][0]-mn0) + __expf(acc[s][1]-mn0);
            e1 += __expf(acc[s][2]-mn1) + __expf(acc[s][3]-mn1);
        }
        e0 += __shfl_xor_sync(0xffffffffu, e0, 1); e0 += __shfl_xor_sync(0xffffffffu, e0, 2);
        e1 += __shfl_xor_sync(0xffffffffu, e1, 1); e1 += __shfl_xor_sync(0xffffffffu, e1, 2);
        s0r = s0r * __expf(m0r - mn0) + e0; m0r = mn0;
        s1r = s1r * __expf(m1r - mn1) + e1; m1r = mn1;
    }
    __syncthreads();
    if ((lane & 3) == 0) {
        const int r0 = wq*16 + (lane >> 2);
        sMS[r0][wk]     = make_float2(m0r, s0r);
        sMS[r0 + 8][wk] = make_float2(m1r, s1r);
    }
    __syncthreads();
    if (tid < 64) {
        float2 a = sMS[tid][0], bb2 = sMS[tid][1];
        float m = fmaxf(a.x, bb2.x);
        float s = a.y * __expf(a.x - m) + bb2.y * __expf(bb2.x - m);
        sFin[tid] = make_float2(m, 1.f / s);
    }
    __syncthreads();

    // ---------------- phase 2: P@V pipeline (kt descending) ----------------
    const int wd = wk;
    auto issueV = [&](int kt, int s) {
        #pragma unroll
        for (int p = 0; p < 2; p++) {
            const int row = srow8 + p*32;
            const uint32_t d = dbase + (uint32_t)s*STAGE_B + 18432 + row*144 + sc16*16;
            const size_t vo = (size_t)(kt*64 + row)*128 + sc16*16;
            cp16(d,        VhG + vo);
            cp16(d + 9216, VlG + vo);
        }
    };
    // exp-normalize 4 rows of raw scores, write probs, stage P hi/lo
    auto stageP = [&](int kt, int s, const float4* pp) {
        uint32_t* Ph = dsm + s*STAGE_W;
        uint32_t* Pl = Ph + 2304;
        #pragma unroll
        for (int i = 0; i < 4; i++) {
            const int row = srow + i*16;
            const float2 st = sFin[row];
            float p0 = __expf(pp[i].x - st.x) * st.y;
            float p1 = __expf(pp[i].y - st.x) * st.y;
            float p2 = __expf(pp[i].z - st.x) * st.y;
            float p3 = __expf(pp[i].w - st.x) * st.y;
            __stcs((float4*)(Sbuf + (size_t)row*SEQ + kt*64 + sq4*4),
                   make_float4(p0, p1, p2, p3));
            uint32_t h0, l0, h1, l1;
            split2(p0, p1, h0, l0);
            split2(p2, p3, h1, l1);
            *(uint2*)&Ph[row*36 + sq4*2] = make_uint2(h0, h1);
            *(uint2*)&Pl[row*36 + sq4*2] = make_uint2(l0, l1);
        }
    };
    auto loadP = [&](int kt, float4* pp) {
        #pragma unroll
        for (int i = 0; i < 4; i++)
            pp[i] = *(const float4*)(Sbuf + (size_t)(srow + i*16)*SEQ + kt*64 + sq4*4);
    };

    float acc2[4][4];
    #pragma unroll
    for (int s = 0; s < 4; s++) { acc2[s][0]=acc2[s][1]=acc2[s][2]=acc2[s][3]=0.f; }
    const uint32_t bt_row = (uint32_t)((lane & 7) + ((lane >> 3) & 1)*8);
    const uint32_t bt_col = ((lane >> 4) & 1)*8;

    float4 pP[4];
    loadP(31, pP); stageP(31, 0, pP); issueV(31, 0); CP_COMMIT();
    loadP(30, pP); stageP(30, 1, pP); issueV(30, 1); CP_COMMIT();
    loadP(29, pP);

    for (int t = 0; t < 32; t++) {
        const int kt = 31 - t;
        CP_WAIT1();
        __syncthreads();
        if (t + 2 < 32) {
            stageP(kt - 2, (t + 2) % 3, pP);
            issueV(kt - 2, (t + 2) % 3);
            if (t + 3 < 32) loadP(kt - 3, pP);
        }
        CP_COMMIT();
        const uint32_t PhB = dbase + (uint32_t)(t % 3)*STAGE_B;
        const uint32_t PlB = PhB + 9216, VhB = PhB + 18432, VlB = PhB + 27648;
        #pragma unroll
        for (int kc = 0; kc < 4; kc++) {
            uint32_t Ph[4], Pl[4];
            ldsm_x4(Ph, PhB + a_byte + kc*32);
            ldsm_x4(Pl, PlB + a_byte + kc*32);
            #pragma unroll
            for (int sp = 0; sp < 2; sp++) {
                uint32_t Bh[4], Bl[4];
                uint32_t boff = (uint32_t)(kc*16 + bt_row)*144
                              + (uint32_t)(wd*32 + sp*16 + bt_col)*2;
                ldsm_x4_t(Bh, VhB + boff);
                ldsm_x4_t(Bl, VlB + boff);
                mma_bf16(acc2[sp*2],   Ph, Bh);   mma_bf16(acc2[sp*2],   Ph, Bl);
                mma_bf16(acc2[sp*2],   Pl, Bh);
                mma_bf16(acc2[sp*2+1], Ph, Bh+2); mma_bf16(acc2[sp*2+1], Ph, Bl+2);
                mma_bf16(acc2[sp*2+1], Pl, Bh+2);
            }
        }
    }
    #pragma unroll
    for (int s = 0; s < 4; s++) {
        const int col = h*64 + wd*32 + s*8 + (lane & 3)*2;
        #pragma unroll
        for (int half = 0; half < 2; half++) {
            const int q = q0 + wq*16 + (lane >> 2) + half*8;
            __stcs((float2*)(ctx_out + (size_t)(b*SEQ + q)*HID + col),
                   make_float2(acc2[s][half*2], acc2[s][half*2+1]));
        }
    }
}

// ---------------------------------------------------------------------------
extern "C" void kernel_launch(void* const* d_in, const int* in_sizes, int n_in,
                              void* d_out, int out_size)
{
    const float* X  = (const float*)d_in[0];
    const float* Wq = (const float*)d_in[1];
    const float* bq = (const float*)d_in[2];
    const float* Wk = (const float*)d_in[3];
    const float* bk = (const float*)d_in[4];
    const float* Wv = (const float*)d_in[5];
    const float* bv = (const float*)d_in[6];

    float* ctx   = (float*)d_out;
    float* probs = (float*)d_out + (size_t)BATCH * SEQ * HID;

    cudaFuncSetAttribute(qkv_t_kernel, cudaFuncAttributeMaxDynamicSharedMemorySize, DSMEM_B);
    cudaFuncSetAttribute(attn_fused_kernel, cudaFuncAttributeMaxDynamicSharedMemorySize, DSMEM_B);

    const int nTot4 = (MTOT * HID + 3 * HID * HID) / 4;
    split_all_kernel<<<nTot4 / 256, 256>>>(X, Wq, Wk, Wv);

    dim3 qkv_grid(HID/64, MTOT/64, 3);
    qkv_t_kernel<<<qkv_grid, 256, DSMEM_B>>>(bq, bk, bv);

    dim3 att_grid(SEQ/64, BH);
    attn_fused_kernel<<<att_grid, 256, DSMEM_B>>>(ctx, probs);
}